// round 7
// baseline (speedup 1.0000x reference)
#include <cuda_runtime.h>

// LearnedBFGSSolver, 3-kernel pipeline (no transpose kernel):
//  K1 kz: U0 = H0*Y, V0 = H0^T*Y for all 3072 (be,t) rows. H0 staged through
//         SMEM tiles in both orientations (dynamic smem); coalesced, conflict-free.
//  K2 ks: per-pair Gram matrices -> 12x12 scalar recursion (warp 0) ->
//         barrier-free per-element rebuild -> factor vectors A, Un.
//  K3 ke: H = H0 + S^T A + Un^T S (rank-24 GEMM), bank-conflict-free layout.

#define NN 192
#define TT 12
#define BE 256

typedef unsigned long long u64;

__device__ float g_U0[BE * TT * NN];   // u0_t = H0 y_t
__device__ float g_V0[BE * TT * NN];   // v0_t = H0^T y_t
__device__ float g_A [BE * TT * NN];   // A[k][j]  = c1_k s_kj - c2_k v_kj
__device__ float g_Un[BE * TT * NN];   // Un[k][i] = -c2_k u_ki

__device__ __forceinline__ u64 fma2(u64 a, u64 b, u64 c) {
    u64 d; asm("fma.rn.f32x2 %0, %1, %2, %3;" : "=l"(d) : "l"(a), "l"(b), "l"(c));
    return d;
}
__device__ __forceinline__ u64 pack2(float lo, float hi) {
    u64 d; asm("mov.b64 %0, {%1, %2};" : "=l"(d) : "f"(lo), "f"(hi));
    return d;
}
__device__ __forceinline__ void unpack2(u64 v, float& lo, float& hi) {
    asm("mov.b64 {%0, %1}, %2;" : "=f"(lo), "=f"(hi) : "l"(v));
}

// ---------------- K1: batched H0*y and H0^T*y, 24 rows per CTA ----------------
// grid 128 (3072/24), 192 threads (thread = output column i). Dynamic smem.
struct KzSmem {
    u64   Yp[NN][TT];      // Yp[j][p] = (Y[r0+2p][j], Y[r0+2p+1][j])
    float st[NN][33];      // st[r][jj] = H0[r][j0+jj]   (U dot, padded)
    float t2[32][NN];      // t2[jj][i] = H0[j0+jj][i]   (V dot)
};

__global__ void __launch_bounds__(192)
kz_kernel(const float* __restrict__ H0g, const float* __restrict__ dgs)
{
    extern __shared__ char kz_raw[];
    KzSmem* sm = reinterpret_cast<KzSmem*>(kz_raw);
    const int tid = threadIdx.x;
    const int r0  = blockIdx.x * 24;  // 24 rows; pairs never straddle t boundary

    #pragma unroll
    for (int p = 0; p < TT; p++) {
        float lo = dgs[(size_t)(r0 + 2 * p) * NN + tid];
        float hi = dgs[(size_t)(r0 + 2 * p + 1) * NN + tid];
        sm->Yp[tid][p] = pack2(lo, hi);
    }

    u64 aU[TT], aV[TT];
    #pragma unroll
    for (int p = 0; p < TT; p++) { aU[p] = 0ull; aV[p] = 0ull; }

    for (int jt = 0; jt < 6; jt++) {
        const int j0 = jt * 32;
        __syncthreads();   // (also orders Yp on first iteration)
        // t2 tile: H0[j0:j0+32][0:192], float4 coalesced
        #pragma unroll
        for (int n = 0; n < 8; n++) {
            int idx = n * 192 + tid;           // float4 index in 32x48
            int row = idx / 48, c4 = (idx % 48) * 4;
            *(float4*)&sm->t2[row][c4] =
                *(const float4*)&H0g[(size_t)(j0 + row) * NN + c4];
        }
        // st tile: H0[0:192][j0:j0+32] (transposed view), scalar coalesced
        #pragma unroll
        for (int n = 0; n < 32; n++) {
            int e = n * 192 + tid;
            int r = e >> 5, jj = e & 31;
            sm->st[r][jj] = H0g[(size_t)r * NN + j0 + jj];
        }
        __syncthreads();

        #pragma unroll 4
        for (int jj = 0; jj < 32; jj++) {
            float h  = sm->st[tid][jj];        // H0[i][j]   -> U0
            float hc = sm->t2[jj][tid];        // H0[j][i]   -> V0
            u64 h2  = pack2(h, h);
            u64 hc2 = pack2(hc, hc);
            const int j = j0 + jj;
            #pragma unroll
            for (int p = 0; p < TT; p++) {
                u64 y2 = sm->Yp[j][p];
                aU[p] = fma2(h2,  y2, aU[p]);
                aV[p] = fma2(hc2, y2, aV[p]);
            }
        }
    }

    #pragma unroll
    for (int p = 0; p < TT; p++) {
        int r = r0 + 2 * p;
        int t = r / BE, be = r % BE;
        float ulo, uhi, vlo, vhi;
        unpack2(aU[p], ulo, uhi);
        unpack2(aV[p], vlo, vhi);
        g_U0[((size_t)be * TT + t) * NN + tid]       = ulo;
        g_U0[((size_t)(be + 1) * TT + t) * NN + tid] = uhi;
        g_V0[((size_t)be * TT + t) * NN + tid]       = vlo;
        g_V0[((size_t)(be + 1) * TT + t) * NN + tid] = vhi;
    }
}

// ---------------- K2: per-pair scalar recursion + factor vectors ----------------
__global__ void __launch_bounds__(192)
ks_kernel(const float* __restrict__ steps, const float* __restrict__ dgs)
{
    __shared__ float sS[TT][NN], sY[TT][NN], sU0[TT][NN], sV0[TT][NN];
    __shared__ float sG1[TT][TT], sW[TT][TT];
    __shared__ float sCU[TT][TT], sCV[TT][TT], sB[TT][TT];
    __shared__ float sC1[TT], sC2[TT];

    const int tid = threadIdx.x;
    const int be  = blockIdx.x;

    for (int idx = tid; idx < TT * NN / 4; idx += 192) {
        int e = idx * 4;
        int k = e / NN, j = e % NN;
        *(float4*)&sS[k][j]  = *(const float4*)&steps[(size_t)(k * BE + be) * NN + j];
        *(float4*)&sY[k][j]  = *(const float4*)&dgs  [(size_t)(k * BE + be) * NN + j];
        *(float4*)&sU0[k][j] = *(const float4*)&g_U0[(size_t)(be * TT + k) * NN + j];
        *(float4*)&sV0[k][j] = *(const float4*)&g_V0[(size_t)(be * TT + k) * NN + j];
    }
    __syncthreads();

    // Grams: G1 = S Y^T, W = V0 Y^T  (2x2 cells per thread, 72 threads)
    if (tid < 72) {
        int which = tid / 36;
        int cell  = tid % 36;
        int k0 = (cell / 6) * 2, t0 = (cell % 6) * 2;
        const float (*P)[NN] = which ? sV0 : sS;
        float a00 = 0.f, a01 = 0.f, a10 = 0.f, a11 = 0.f;
        for (int j = 0; j < NN; j += 4) {
            float4 p0 = *(const float4*)&P[k0][j];
            float4 p1 = *(const float4*)&P[k0 + 1][j];
            float4 q0 = *(const float4*)&sY[t0][j];
            float4 q1 = *(const float4*)&sY[t0 + 1][j];
            a00 += p0.x * q0.x + p0.y * q0.y + p0.z * q0.z + p0.w * q0.w;
            a01 += p0.x * q1.x + p0.y * q1.y + p0.z * q1.z + p0.w * q1.w;
            a10 += p1.x * q0.x + p1.y * q0.y + p1.z * q0.z + p1.w * q0.w;
            a11 += p1.x * q1.x + p1.y * q1.y + p1.z * q1.z + p1.w * q1.w;
        }
        float (*G)[TT] = which ? sW : sG1;
        G[k0][t0] = a00;     G[k0][t0 + 1] = a01;
        G[k0 + 1][t0] = a10; G[k0 + 1][t0 + 1] = a11;
    }
    __syncthreads();

    // Warp-0 scalar recursion, lane = column t
    if (tid < 32) {
        const int t = (tid < TT) ? tid : (TT - 1);
        float G1c[TT], Wc[TT], Wr[TT];
        float d2c[TT], d3c[TT];
        float c1v[TT], c2v[TT];
        float cuL[TT], cvL[TT], bL[TT];
        #pragma unroll
        for (int m = 0; m < TT; m++) {
            G1c[m] = sG1[m][t];
            Wc[m]  = sW[m][t];
            Wr[m]  = sW[t][m];
            cuL[m] = 0.f; cvL[m] = 0.f; bL[m] = 0.f;
        }
        #pragma unroll
        for (int k = 0; k < TT; k++) {
            if (k > 0) {
                const int m = k - 1;
                cuL[m] = c1v[m] * G1c[m] - c2v[m] * d2c[m];
                cvL[m] = c1v[m] * G1c[m] - c2v[m] * d3c[m];
                bL[m]  = -c2v[m] * G1c[m];
            }
            float x2 = Wc[k], x3 = Wr[k];
            #pragma unroll
            for (int m = 0; m < TT - 1; m++) {
                if (m < k) {
                    float cvk = __shfl_sync(0xFFFFFFFFu, cvL[m], k);
                    float cuk = __shfl_sync(0xFFFFFFFFu, cuL[m], k);
                    float bk  = __shfl_sync(0xFFFFFFFFu, bL[m],  k);
                    x2 += cvk * G1c[m] + bk * d2c[m];
                    x3 += cuk * G1c[m] + bk * d3c[m];
                }
            }
            d2c[k] = x2;
            d3c[k] = x3;
            float yHy  = __shfl_sync(0xFFFFFFFFu, x3, k);
            float sdot = __shfl_sync(0xFFFFFFFFu, G1c[k], k);
            float ic = (sdot != 0.0f) ? (1.0f / sdot) : 0.0f;
            c2v[k] = ic;
            c1v[k] = (sdot + yHy) * ic * ic;
        }
        if (tid < TT) {
            #pragma unroll
            for (int m = 0; m < TT - 1; m++) {
                sCU[m][t] = cuL[m];
                sCV[m][t] = cvL[m];
                sB[m][t]  = bL[m];
            }
        }
        if (tid == 0) {
            #pragma unroll
            for (int m = 0; m < TT; m++) { sC1[m] = c1v[m]; sC2[m] = c2v[m]; }
        }
    }
    __syncthreads();

    // Barrier-free per-element rebuild of u_t, v_t; emit A, Un
    {
        const int i = tid;
        float s[TT], u[TT], v[TT];
        #pragma unroll
        for (int k = 0; k < TT; k++) {
            s[k] = sS[k][i];
            u[k] = sU0[k][i];
            v[k] = sV0[k][i];
        }
        #pragma unroll
        for (int t = 0; t < TT; t++) {
            #pragma unroll
            for (int k = 0; k < TT - 1; k++) {
                if (k < t) {
                    float bb = sB[k][t];
                    u[t] += sCU[k][t] * s[k] + bb * u[k];
                    v[t] += sCV[k][t] * s[k] + bb * v[k];
                }
            }
            float c1 = sC1[t], c2 = sC2[t];
            g_A [(size_t)(be * TT + t) * NN + i] = c1 * s[t] - c2 * v[t];
            g_Un[(size_t)(be * TT + t) * NN + i] = -c2 * u[t];
        }
    }
}

// ---------------- K3: rank-24 epilogue GEMM ----------------
// grid = 256 pairs * 3 row-blocks (64 rows); 192 threads; 8x8 f32x2 tiles.
// Layout: cg = tid>>3 (column group: 8 lanes broadcast same column address),
//         rg = tid&7 (row group) -> column LDS conflict-free, row LDS ~2-way.
__global__ void __launch_bounds__(192)
ke_kernel(const float* __restrict__ H0g,
          const float* __restrict__ steps,
          float* __restrict__ out)
{
    __shared__ float sA[TT][NN];
    __shared__ float sS[TT][NN];
    __shared__ float sUn[TT][64];
    const int tid  = threadIdx.x;
    const int be   = blockIdx.x / 3;
    const int rblk = (blockIdx.x % 3) * 64;

    for (int idx = tid; idx < TT * NN / 4; idx += 192) {
        int e = idx * 4;
        int k = e / NN, j = e % NN;
        *(float4*)&sA[k][j] = *(const float4*)&g_A[(size_t)(be * TT + k) * NN + j];
        *(float4*)&sS[k][j] = *(const float4*)&steps[(size_t)(k * BE + be) * NN + j];
    }
    {
        int e = tid * 4;               // TT*64/4 = 192 float4 loads, 1/thread
        int k = e / 64, r = e % 64;
        *(float4*)&sUn[k][r] = *(const float4*)&g_Un[(size_t)(be * TT + k) * NN + rblk + r];
    }
    __syncthreads();

    const int cg = tid >> 3, rg = tid & 7;
    const int c0  = cg * 8;
    const int lr0 = rg * 8;
    const int grow = rblk + lr0;
    float* ob = out + (size_t)be * NN * NN;

    u64 acc[8][4];
    #pragma unroll
    for (int r = 0; r < 8; r++) {
        ulonglong2 h01 = *(const ulonglong2*)&H0g[(size_t)(grow + r) * NN + c0];
        ulonglong2 h23 = *(const ulonglong2*)&H0g[(size_t)(grow + r) * NN + c0 + 4];
        acc[r][0] = h01.x; acc[r][1] = h01.y; acc[r][2] = h23.x; acc[r][3] = h23.y;
    }
    #pragma unroll
    for (int k = 0; k < TT; k++) {
        ulonglong2 a01 = *(ulonglong2*)&sA[k][c0];
        ulonglong2 a23 = *(ulonglong2*)&sA[k][c0 + 4];
        ulonglong2 s01 = *(ulonglong2*)&sS[k][c0];
        ulonglong2 s23 = *(ulonglong2*)&sS[k][c0 + 4];
        u64 av[4] = {a01.x, a01.y, a23.x, a23.y};
        u64 sv[4] = {s01.x, s01.y, s23.x, s23.y};
        float4 sr0 = *(float4*)&sS[k][grow];
        float4 sr1 = *(float4*)&sS[k][grow + 4];
        float4 ur0 = *(float4*)&sUn[k][lr0];
        float4 ur1 = *(float4*)&sUn[k][lr0 + 4];
        float srow[8] = {sr0.x, sr0.y, sr0.z, sr0.w, sr1.x, sr1.y, sr1.z, sr1.w};
        float urow[8] = {ur0.x, ur0.y, ur0.z, ur0.w, ur1.x, ur1.y, ur1.z, ur1.w};
        #pragma unroll
        for (int r = 0; r < 8; r++) {
            u64 s2 = pack2(srow[r], srow[r]);
            u64 u2 = pack2(urow[r], urow[r]);
            #pragma unroll
            for (int c = 0; c < 4; c++) {
                acc[r][c] = fma2(s2, av[c], acc[r][c]);
                acc[r][c] = fma2(u2, sv[c], acc[r][c]);
            }
        }
    }
    #pragma unroll
    for (int r = 0; r < 8; r++) {
        *(ulonglong2*)&ob[(size_t)(grow + r) * NN + c0] =
            make_ulonglong2(acc[r][0], acc[r][1]);
        *(ulonglong2*)&ob[(size_t)(grow + r) * NN + c0 + 4] =
            make_ulonglong2(acc[r][2], acc[r][3]);
    }
}

extern "C" void kernel_launch(void* const* d_in, const int* in_sizes, int n_in,
                              void* d_out, int out_size) {
    const float* H0    = (const float*)d_in[0];   // inv_hessian [192,192]
    const float* steps = (const float*)d_in[1];   // [12,8,32,192]
    const float* dgs   = (const float*)d_in[2];   // [12,8,32,192]
    float* out = (float*)d_out;                   // [8,32,192,192]

    int kz_smem = (int)sizeof(KzSmem);
    cudaFuncSetAttribute(kz_kernel,
                         cudaFuncAttributeMaxDynamicSharedMemorySize, kz_smem);
    kz_kernel<<<128, 192, kz_smem>>>(H0, dgs);
    ks_kernel<<<BE, 192>>>(steps, dgs);
    ke_kernel<<<BE * 3, 192>>>(H0, steps, out);
}